// round 14
// baseline (speedup 1.0000x reference)
#include <cuda_runtime.h>
#include <cuda_bf16.h>
#include <math.h>

// Problem constants
#define H2 48
#define W2 48
#define NPIX 2304           // 48*48
#define CCH 128             // channels
#define NB 2                // batch
#define H1 96
#define W1 96
#define NJ 2048             // 16 * 128  ((a,b) x c)
#define OPIX 9216           // 96*96

typedef unsigned long long u64;

// ---------------- scratch (device globals; referenced ONLY from device code) ----------------
__device__ __align__(16) float g_C[(size_t)NB * NPIX * NPIX];     // pixel gram C = X^T X [n][p][q]
__device__ __align__(16) float g_Ah[(size_t)NB * NPIX * NPIX];    // att hi (tf32-rounded)
__device__ __align__(16) float g_Al[(size_t)NB * NPIX * NPIX];    // att lo (tf32-rounded)
__device__ __align__(16) float g_Wh[(size_t)NB * NPIX * NJ];      // im2col(x1) hi
__device__ __align__(16) float g_Wl[(size_t)NB * NPIX * NJ];      // im2col(x1) lo
__device__ __align__(16) float g_T[(size_t)NB * NPIX * NJ];       // paste gemm out
__device__ __align__(16) float g_y[(size_t)NB * CCH * OPIX];      // paste result [n][c][96*96]
__device__ float g_s2[NB * NPIX];                                 // per-pixel channel sumsq
__device__ float g_denom[NB * NPIX];
__device__ float g_mm[NB * NPIX];
__device__ int g_sel;   // 0: first 4608-tensor is binary mask; 1: it's mask_all

// ---------------- helpers ----------------
__device__ __forceinline__ u64 pack2(float lo, float hi) {
    u64 r; asm("mov.b64 %0, {%1, %2};" : "=l"(r) : "f"(lo), "f"(hi)); return r;
}
__device__ __forceinline__ void fma2(u64& d, u64 a, u64 b) {
    asm("fma.rn.f32x2 %0, %1, %2, %0;" : "+l"(d) : "l"(a), "l"(b));
}
__device__ __forceinline__ float2 unpack2(u64 v) {
    float2 f; asm("mov.b64 {%0, %1}, %2;" : "=f"(f.x), "=f"(f.y) : "l"(v)); return f;
}
__device__ __forceinline__ void split_tf32(float v, float& h, float& l) {
    unsigned hb; asm("cvt.rna.tf32.f32 %0, %1;" : "=r"(hb) : "f"(v));
    h = __uint_as_float(hb);
    float r = v - h;                     // exact (Sterbenz: h within 2^-11 of v)
    unsigned lb; asm("cvt.rna.tf32.f32 %0, %1;" : "=r"(lb) : "f"(r));
    l = __uint_as_float(lb);
}
__device__ __forceinline__ void mma8(float* d, const unsigned* a, const unsigned* b) {
    asm volatile("mma.sync.aligned.m16n8k8.row.col.f32.tf32.tf32.f32 "
        "{%0,%1,%2,%3}, {%4,%5,%6,%7}, {%8,%9}, {%0,%1,%2,%3};"
        : "+f"(d[0]), "+f"(d[1]), "+f"(d[2]), "+f"(d[3])
        : "r"(a[0]), "r"(a[1]), "r"(a[2]), "r"(a[3]), "r"(b[0]), "r"(b[1]));
}

// ---------------- K0: detect which 4608-tensor is the binary mask ----------------
__global__ __launch_bounds__(256) void k_detect(const float* __restrict__ mA) {
    __shared__ int nonbin;
    if (threadIdx.x == 0) nonbin = 0;
    __syncthreads();
    int local = 0;
    for (int i = threadIdx.x; i < NB * NPIX; i += 256) {
        float v = mA[i];
        if (v != 0.0f && v != 1.0f) local = 1;
    }
    if (local) atomicOr(&nonbin, 1);
    __syncthreads();
    if (threadIdx.x == 0) g_sel = nonbin;   // nonbinary -> mA is mask_all
}

// ---------------- K1: per-pixel channel sum of squares ----------------
__global__ __launch_bounds__(256) void k_s2(const float* __restrict__ x2) {
    int p = blockIdx.x * 256 + threadIdx.x;       // < 2304
    int n = blockIdx.y;
    float s = 0.f;
    #pragma unroll 4
    for (int c = 0; c < CCH; c++) {
        float v = x2[((size_t)(n * CCH + c)) * NPIX + p];
        s += v * v;
    }
    g_s2[n * NPIX + p] = s;
}

// ---------------- K2: per-q denom + mask flags ----------------
__global__ __launch_bounds__(256) void k_prep(const float* __restrict__ mA,
                                              const float* __restrict__ mB) {
    const float* maskb = (g_sel == 0) ? mA : mB;   // binary one
    int q = blockIdx.x * 256 + threadIdx.x;   // < 2304
    int n = blockIdx.y;
    int qy = q / W2, qx = q % W2;
    float ms = 0.f, d2 = 0.f;
    #pragma unroll
    for (int dy = -1; dy <= 1; dy++) {
        int ry = qy + dy;
        if ((unsigned)ry >= H2) continue;
        #pragma unroll
        for (int dx = -1; dx <= 1; dx++) {
            int rx = qx + dx;
            if ((unsigned)rx < W2) {
                int idx = n * NPIX + ry * W2 + rx;
                ms += maskb[idx];
                d2 += g_s2[idx];
            }
        }
    }
    g_denom[n * NPIX + q] = fmaxf(sqrtf(d2), 1e-4f);
    g_mm[n * NPIX + q] = (ms == 0.0f) ? 1.0f : 0.0f;
}

// ---------------- gram SGEMM (FFMA2): C = X^T X, X = x2 [K=128][M=2304] ----------------
__global__ __launch_bounds__(256) void k_gram(const float* __restrict__ Xin) {
    const size_t z = blockIdx.z;
    const float* A = Xin + z * ((size_t)CCH * NPIX);
    float* C = g_C + z * ((size_t)NPIX * NPIX);

    const int n0 = blockIdx.x * 128;
    const int m0 = blockIdx.y * 128;

    __shared__ float As[8][128];
    __shared__ float Bs[8][128];

    const int t = threadIdx.x;
    const int tx = t & 15;
    const int ty = t >> 4;
    const int bk_row = t >> 5;
    const int bk_col = (t & 31) * 4;

    u64 acc2[4][8];
    #pragma unroll
    for (int i = 0; i < 4; i++)
        #pragma unroll
        for (int j = 0; j < 8; j++) acc2[i][j] = 0ull;

    for (int k0 = 0; k0 < CCH; k0 += 8) {
        float4 va = *(const float4*)&A[(size_t)(k0 + bk_row) * NPIX + m0 + bk_col];
        *(float4*)&As[bk_row][bk_col] = va;
        float4 vb = *(const float4*)&A[(size_t)(k0 + bk_row) * NPIX + n0 + bk_col];
        *(float4*)&Bs[bk_row][bk_col] = vb;
        __syncthreads();

        #pragma unroll
        for (int kk = 0; kk < 8; kk++) {
            float a[8], b[8];
            *(float4*)(a + 0) = *(float4*)&As[kk][ty * 8 + 0];
            *(float4*)(a + 4) = *(float4*)&As[kk][ty * 8 + 4];
            *(float4*)(b + 0) = *(float4*)&Bs[kk][tx * 8 + 0];
            *(float4*)(b + 4) = *(float4*)&Bs[kk][tx * 8 + 4];
            u64 ap[4], bp[8];
            #pragma unroll
            for (int i = 0; i < 4; i++) ap[i] = pack2(a[2 * i], a[2 * i + 1]);
            #pragma unroll
            for (int j = 0; j < 8; j++) bp[j] = pack2(b[j], b[j]);
            #pragma unroll
            for (int i = 0; i < 4; i++)
                #pragma unroll
                for (int j = 0; j < 8; j++) fma2(acc2[i][j], ap[i], bp[j]);
        }
        __syncthreads();
    }

    #pragma unroll
    for (int i = 0; i < 4; i++) {
        float r0[8], r1[8];
        #pragma unroll
        for (int j = 0; j < 8; j++) {
            float2 v = unpack2(acc2[i][j]);
            r0[j] = v.x;
            r1[j] = v.y;
        }
        float* c0 = &C[(size_t)(m0 + ty * 8 + 2 * i + 0) * NPIX + n0 + tx * 8];
        float* c1 = &C[(size_t)(m0 + ty * 8 + 2 * i + 1) * NPIX + n0 + tx * 8];
        *(float4*)(c0 + 0) = *(float4*)&r0[0];
        *(float4*)(c0 + 4) = *(float4*)&r0[4];
        *(float4*)(c1 + 0) = *(float4*)&r1[0];
        *(float4*)(c1 + 4) = *(float4*)&r1[4];
    }
}

// ---------------- K3: im2col of x1 (kernel 4, stride 2, pad 1) + tf32 split ----------------
__global__ __launch_bounds__(256) void k_im2col(const float* __restrict__ x1) {
    int q = blockIdx.x;
    int n = blockIdx.y;
    int qy = q / W2, qx = q % W2;
    size_t base = ((size_t)n * NPIX + q) * NJ;
    for (int j = threadIdx.x; j < NJ; j += 256) {
        int c = j & 127;
        int ab = j >> 7;
        int a = ab >> 2, b = ab & 3;
        int ry = 2 * qy + a - 1;
        int rx = 2 * qx + b - 1;
        float v = 0.f;
        if ((unsigned)ry < H1 && (unsigned)rx < W1)
            v = x1[((size_t)(n * CCH + c) * H1 + ry) * W1 + rx];
        float h, l;
        split_tf32(v, h, l);
        g_Wh[base + j] = h;
        g_Wl[base + j] = l;
    }
}

// ---------------- K4: score assembly from gram + softmax + boost + remask + split ----------------
__global__ __launch_bounds__(256) void k_attn(const float* __restrict__ mA,
                                              const float* __restrict__ mB) {
    const float* maskall = (g_sel == 0) ? mB : mA;   // non-binary
    const int p = blockIdx.x;
    const int n = blockIdx.y;
    const int py = p / W2, px = p % W2;
    const int t = threadIdx.x;

    __shared__ float red[8];
    __shared__ float bcast;

    const float ma = maskall[n * NPIX + p];
    const float* Cb = g_C + (size_t)n * NPIX * NPIX;

    float z[9];
    float mmv[9];
    #pragma unroll
    for (int i = 0; i < 9; i++) {
        int q = i * 256 + t;
        int qy = q / W2, qx = q % W2;

        // score S[p][q] = sum over valid offsets o of C[p+o, q+o]
        float s = 0.f;
        #pragma unroll
        for (int dy = -1; dy <= 1; dy++) {
            int ry = py + dy, sy = qy + dy;
            if ((unsigned)ry >= H2 || (unsigned)sy >= H2) continue;
            #pragma unroll
            for (int dx = -1; dx <= 1; dx++) {
                int rx = px + dx, sx = qx + dx;
                if ((unsigned)rx < W2 && (unsigned)sx < W2)
                    s += Cb[(size_t)(ry * W2 + rx) * NPIX + sy * W2 + sx];
            }
        }
        float mq = g_mm[n * NPIX + q];
        mmv[i] = mq;
        z[i] = s / g_denom[n * NPIX + q] * mq * ma * 10.0f;
    }

    // block max
    float m = z[0];
    #pragma unroll
    for (int i = 1; i < 9; i++) m = fmaxf(m, z[i]);
    #pragma unroll
    for (int o = 16; o > 0; o >>= 1) m = fmaxf(m, __shfl_xor_sync(0xffffffffu, m, o));
    if ((t & 31) == 0) red[t >> 5] = m;
    __syncthreads();
    if (t == 0) {
        float mm = red[0];
        #pragma unroll
        for (int w = 1; w < 8; w++) mm = fmaxf(mm, red[w]);
        bcast = mm;
    }
    __syncthreads();
    const float zmax = bcast;
    __syncthreads();

    float e[9];
    float es = 0.f;
    #pragma unroll
    for (int i = 0; i < 9; i++) {
        e[i] = __expf(z[i] - zmax);
        es += e[i];
    }
    #pragma unroll
    for (int o = 16; o > 0; o >>= 1) es += __shfl_xor_sync(0xffffffffu, es, o);
    if ((t & 31) == 0) red[t >> 5] = es;
    __syncthreads();
    if (t == 0) {
        float ss = 0.f;
        #pragma unroll
        for (int w = 0; w < 8; w++) ss += red[w];
        bcast = ss;
    }
    __syncthreads();
    const float inv = 1.0f / bcast;

    size_t rbase = (size_t)n * NPIX * NPIX + (size_t)p * NPIX;
    #pragma unroll
    for (int i = 0; i < 9; i++) {
        int q = i * 256 + t;
        float v = e[i] * inv;
        bool nb = (q == p - 1 && px > 0) || (q == p + 1 && px < W2 - 1) ||
                  (q == p - W2 && py > 0) || (q == p + W2 && py < H2 - 1);
        if (nb) v *= 1.5f;
        v = v * mmv[i] * ma;
        v = (v >= 1e-8f) ? v : 1e-8f;   // NaN-explicit clamp
        float h, l;
        split_tf32(v, h, l);
        g_Ah[rbase + q] = h;
        g_Al[rbase + q] = l;
    }
}

// ---------------- K5: paste GEMM via tf32 mma.sync (3xTF32) ----------------
// C = att[2304x2304] * W[2304x2048]; block 128x128, k-tile 16, 8 warps (64x32 each)
#define KTILE 16
__global__ __launch_bounds__(256) void k_mma() {
    const size_t z = blockIdx.z;
    const float* Ahg = g_Ah + z * ((size_t)NPIX * NPIX);
    const float* Alg = g_Al + z * ((size_t)NPIX * NPIX);
    const float* Bhg = g_Wh + z * ((size_t)NPIX * NJ);
    const float* Blg = g_Wl + z * ((size_t)NPIX * NJ);
    float* C = g_T + z * ((size_t)NPIX * NJ);

    const int n0 = blockIdx.x * 128;
    const int m0 = blockIdx.y * 128;

    __shared__ float Ahs[KTILE][136], Als[KTILE][136];
    __shared__ float Bhs[KTILE][136], Bls[KTILE][136];

    const int t = threadIdx.x;
    const int lane = t & 31;
    const int wid = t >> 5;
    const int wm = (wid & 1) * 64;    // warp M offset
    const int wn = (wid >> 1) * 32;   // warp N offset

    float acc[4][4][4];
    #pragma unroll
    for (int i = 0; i < 4; i++)
        #pragma unroll
        for (int j = 0; j < 4; j++)
            #pragma unroll
            for (int k = 0; k < 4; k++) acc[i][j][k] = 0.f;

    const int ar = t & 127;           // A row 0..127
    const int ac = (t >> 7) * 8;      // A col base 0/8
    const int bk = t >> 4;            // B k row 0..15
    const int bn = (t & 15) * 8;      // B n base

    for (int k0 = 0; k0 < NPIX; k0 += KTILE) {
        // A tiles (transpose to [k][m]); conflict-free: lanes in warp share ac, consecutive ar
        {
            const float* pa = &Ahg[(size_t)(m0 + ar) * NPIX + k0 + ac];
            float4 h0 = *(const float4*)(pa + 0);
            float4 h1 = *(const float4*)(pa + 4);
            Ahs[ac + 0][ar] = h0.x; Ahs[ac + 1][ar] = h0.y; Ahs[ac + 2][ar] = h0.z; Ahs[ac + 3][ar] = h0.w;
            Ahs[ac + 4][ar] = h1.x; Ahs[ac + 5][ar] = h1.y; Ahs[ac + 6][ar] = h1.z; Ahs[ac + 7][ar] = h1.w;
            const float* pl = &Alg[(size_t)(m0 + ar) * NPIX + k0 + ac];
            float4 l0 = *(const float4*)(pl + 0);
            float4 l1 = *(const float4*)(pl + 4);
            Als[ac + 0][ar] = l0.x; Als[ac + 1][ar] = l0.y; Als[ac + 2][ar] = l0.z; Als[ac + 3][ar] = l0.w;
            Als[ac + 4][ar] = l1.x; Als[ac + 5][ar] = l1.y; Als[ac + 6][ar] = l1.z; Als[ac + 7][ar] = l1.w;
        }
        // B tiles (direct [k][n])
        {
            const float* pb = &Bhg[(size_t)(k0 + bk) * NJ + n0 + bn];
            *(float4*)&Bhs[bk][bn + 0] = *(const float4*)(pb + 0);
            *(float4*)&Bhs[bk][bn + 4] = *(const float4*)(pb + 4);
            const float* pbl = &Blg[(size_t)(k0 + bk) * NJ + n0 + bn];
            *(float4*)&Bls[bk][bn + 0] = *(const float4*)(pbl + 0);
            *(float4*)&Bls[bk][bn + 4] = *(const float4*)(pbl + 4);
        }
        __syncthreads();

        #pragma unroll
        for (int k8 = 0; k8 < 2; k8++) {
            const int kb = k8 * 8;
            const int r = lane >> 2;      // 0..7
            const int kc = lane & 3;      // 0..3
            unsigned ah[4][4], al[4][4], bh[4][2], bl[4][2];
            #pragma unroll
            for (int mi = 0; mi < 4; mi++) {
                int m = wm + mi * 16;
                ah[mi][0] = __float_as_uint(Ahs[kb + kc][m + r]);
                ah[mi][1] = __float_as_uint(Ahs[kb + kc][m + r + 8]);
                ah[mi][2] = __float_as_uint(Ahs[kb + kc + 4][m + r]);
                ah[mi][3] = __float_as_uint(Ahs[kb + kc + 4][m + r + 8]);
                al[mi][0] = __float_as_uint(Als[kb + kc][m + r]);
                al[mi][1] = __float_as_uint(Als[kb + kc][m + r + 8]);
                al[mi][2] = __float_as_uint(Als[kb + kc + 4][m + r]);
                al[mi][3] = __float_as_uint(Als[kb + kc + 4][m + r + 8]);
            }
            #pragma unroll
            for (int ni = 0; ni < 4; ni++) {
                int nn = wn + ni * 8;
                bh[ni][0] = __float_as_uint(Bhs[kb + kc][nn + r]);
                bh[ni][1] = __float_as_uint(Bhs[kb + kc + 4][nn + r]);
                bl[ni][0] = __float_as_uint(Bls[kb + kc][nn + r]);
                bl[ni][1] = __float_as_uint(Bls[kb + kc + 4][nn + r]);
            }
            #pragma unroll
            for (int mi = 0; mi < 4; mi++)
                #pragma unroll
                for (int ni = 0; ni < 4; ni++) {
                    mma8(acc[mi][ni], ah[mi], bh[ni]);
                    mma8(acc[mi][ni], al[mi], bh[ni]);
                    mma8(acc[mi][ni], ah[mi], bl[ni]);
                }
        }
        __syncthreads();
    }

    // epilogue: c0 (r, 2c), c1 (r, 2c+1), c2 (r+8, 2c), c3 (r+8, 2c+1)
    #pragma unroll
    for (int mi = 0; mi < 4; mi++) {
        #pragma unroll
        for (int ni = 0; ni < 4; ni++) {
            int row = m0 + wm + mi * 16 + (lane >> 2);
            int col = n0 + wn + ni * 8 + (lane & 3) * 2;
            float2 v01 = make_float2(acc[mi][ni][0], acc[mi][ni][1]);
            float2 v23 = make_float2(acc[mi][ni][2], acc[mi][ni][3]);
            *(float2*)&C[(size_t)row * NJ + col] = v01;
            *(float2*)&C[(size_t)(row + 8) * NJ + col] = v23;
        }
    }
}

// ---------------- K6: col2im (transposed-conv gather) ----------------
__global__ __launch_bounds__(128) void k_col2im() {
    int o = blockIdx.x;             // 0..9215
    int n = blockIdx.y;
    int c = threadIdx.x;            // 0..127
    int oy = o / W1, ox = o % W1;
    int a0 = (oy + 1) & 1, b0 = (ox + 1) & 1;
    const float* Tb = g_T + (size_t)n * NPIX * NJ;
    float s = 0.f;
    #pragma unroll
    for (int da = 0; da < 2; da++) {
        int a = a0 + 2 * da;
        int iy2 = oy + 1 - a;
        if (iy2 < 0) continue;
        int iy = iy2 >> 1;
        if (iy >= H2) continue;
        #pragma unroll
        for (int db = 0; db < 2; db++) {
            int b = b0 + 2 * db;
            int ix2 = ox + 1 - b;
            if (ix2 < 0) continue;
            int ix = ix2 >> 1;
            if (ix >= W2) continue;
            s += Tb[(size_t)(iy * W2 + ix) * NJ + (a * 4 + b) * 128 + c];
        }
    }
    g_y[((size_t)(n * CCH + c)) * OPIX + o] = 0.25f * s;
}

// ---------------- K7: fused group dilated 3x3 convs + bias + relu ----------------
__global__ __launch_bounds__(128) void k_fuse(const float* __restrict__ fw,
                                              const float* __restrict__ fb,
                                              float* __restrict__ out) {
    const int chunk = blockIdx.x;   // 0..17 (512 pixels each)
    const int g = blockIdx.y;       // 0..3
    const int n = blockIdx.z;
    const int t = threadIdx.x;      // 0..127
    const int d = 1 << g;

    __shared__ float sfw[32 * 9 * 16];  // [c_local][tap][oc]

    int P[4], OY[4], OX[4];
    #pragma unroll
    for (int i = 0; i < 4; i++) {
        P[i] = chunk * 512 + i * 128 + t;
        OY[i] = P[i] / W1;
        OX[i] = P[i] % W1;
    }

    float acc[4][16];
    #pragma unroll
    for (int i = 0; i < 4; i++)
        #pragma unroll
        for (int oc = 0; oc < 16; oc++) acc[i][oc] = 0.f;

    for (int cc0 = 0; cc0 < CCH; cc0 += 32) {
        __syncthreads();
        for (int s = t; s < 32 * 9 * 16; s += 128) {
            int oc = s & 15;
            int tap = (s >> 4) % 9;
            int cl = s / 144;
            sfw[s] = fw[((size_t)(g * 16 + oc) * CCH + cc0 + cl) * 9 + tap];
        }
        __syncthreads();

        for (int cl = 0; cl < 32; cl++) {
            const float* yb = &g_y[((size_t)(n * CCH + cc0 + cl)) * OPIX];
            #pragma unroll
            for (int tap = 0; tap < 9; tap++) {
                int ky = tap / 3 - 1, kx = tap % 3 - 1;
                float yv[4];
                #pragma unroll
                for (int i = 0; i < 4; i++) {
                    int iy = OY[i] + d * ky, ix = OX[i] + d * kx;
                    yv[i] = ((unsigned)iy < H1 && (unsigned)ix < W1) ? yb[iy * W1 + ix] : 0.f;
                }
                const float* wr = &sfw[cl * 144 + tap * 16];
                #pragma unroll
                for (int oc = 0; oc < 16; oc++) {
                    float w = wr[oc];
                    #pragma unroll
                    for (int i = 0; i < 4; i++) acc[i][oc] += yv[i] * w;
                }
            }
        }
    }

    #pragma unroll
    for (int oc = 0; oc < 16; oc++) {
        float b = fb[g * 16 + oc];
        #pragma unroll
        for (int i = 0; i < 4; i++) {
            out[((size_t)(n * 64 + g * 16 + oc)) * OPIX + P[i]] = fmaxf(acc[i][oc] + b, 0.f);
        }
    }
}

// ---------------- launch ----------------
extern "C" void kernel_launch(void* const* d_in, const int* in_sizes, int n_in,
                              void* d_out, int out_size) {
    const float* x1 = 0;
    const float* x2 = 0;
    const float* mA = 0;
    const float* mB = 0;
    const float* fuse_w = 0;
    const float* fuse_b = 0;
    for (int i = 0; i < n_in; i++) {
        int sz = in_sizes[i];
        const float* p = (const float*)d_in[i];
        if (sz == 2359296) x1 = p;
        else if (sz == 589824) x2 = p;
        else if (sz == 73728) fuse_w = p;
        else if (sz == 64) fuse_b = p;
        else if (sz == 4608) {
            if (!mA) mA = p;
            else mB = p;
        }
    }
    if (!x1 || !x2 || !mA || !mB || !fuse_w || !fuse_b) {
        x1 = (const float*)d_in[0];
        x2 = (const float*)d_in[1];
        mA = (const float*)d_in[2];
        mB = (const float*)d_in[3];
        fuse_w = (const float*)d_in[4];
        fuse_b = (const float*)d_in[5];
    }
    float* out = (float*)d_out;                     // (2,64,96,96)

    // 0. decide which 4608-tensor is the binary mask
    k_detect<<<1, 256>>>(mA);

    // 1. per-pixel sum of squares (for patch norms)
    k_s2<<<dim3(9, NB), 256>>>(x2);

    // 2. pixel gram C = X^T X : M=N=2304, K=128
    k_gram<<<dim3(18, 18, NB), 256>>>(x2);

    // 3. per-q denom + mask flags
    k_prep<<<dim3(9, NB), 256>>>(mA, mB);

    // 4. im2col of x1 + tf32 split (independent)
    k_im2col<<<dim3(NPIX, NB), 256>>>(x1);

    // 5. score assembly + softmax + boost + remask + tf32 split
    k_attn<<<dim3(NPIX, NB), 256>>>(mA, mB);

    // 6. paste GEMM on tensor pipe: T = att * W (3xTF32)
    k_mma<<<dim3(16, 18, NB), 256>>>();

    // 7. col2im + /4
    k_col2im<<<dim3(OPIX, NB), 128>>>();

    // 8. fuse convs
    k_fuse<<<dim3(18, 4, NB), 128>>>(fuse_w, fuse_b, out);
}